// round 4
// baseline (speedup 1.0000x reference)
#include <cuda_runtime.h>
#include <math.h>

#define B 4
#define S 4096
#define F 128
#define GAMMA 0.96875f
#define NTILE 64
#define TPB 256
#define NQTILES ((B*S)/NTILE)   // 256
#define MAXDJ 8                 // include key tiles with (i - j) <= 8; gamma^513 ~ 8e-8

#define QPITCH 68
#define VPITCH 132
#define SPITCH 65
#define XT_PITCH 68

// ---------------- scratch (static device allocations only) ----------------
__device__ __align__(16) float g_cos[S*F];
__device__ __align__(16) float g_sin[S*F];
__device__ __align__(16) float g_decay[1024];
__device__ __align__(16) float g_Wt[3][F*F];
__device__ __align__(16) float g_qc[B*S*F];
__device__ __align__(16) float g_qs[B*S*F];
__device__ __align__(16) float g_kc[B*S*F];
__device__ __align__(16) float g_ks[B*S*F];
__device__ __align__(16) float g_v [B*S*F];

// ---------------- init: cos/sin tables, decay table ----------------
__global__ void init_tables(const float* __restrict__ theta) {
    int bx = blockIdx.x;
    int t  = threadIdx.x;
    if (bx < S) {
        float mt = (float)(bx + 1) * theta[t];
        float sn, cs;
        sincosf(mt, &sn, &cs);
        g_cos[bx*F + t] = cs;
        g_sin[bx*F + t] = sn;
    } else {
        int e = (bx - S) * 128 + t;
        if (e < 1024) g_decay[e] = powf(GAMMA, (float)e);
    }
}

// ---------------- transpose weights once: Wt[f][c] = W[c][f] ----------------
__global__ void transpose_w(const float* __restrict__ Wq,
                            const float* __restrict__ Wk,
                            const float* __restrict__ Wv) {
    const float* W = (blockIdx.x == 0) ? Wq : ((blockIdx.x == 1) ? Wk : Wv);
    float* Wt = g_Wt[blockIdx.x];
    for (int idx = threadIdx.x; idx < F*F; idx += blockDim.x) {
        int c = idx & (F-1);
        int f = idx >> 7;
        Wt[idx] = W[c*F + f];   // idx = f*F + c
    }
}

// ---------------- fused QKV projection + cos/sin modulation ----------------
// grid: 256 blocks (64 rows each), 256 threads; thread tile 4 rows x 8 cols
__global__ void __launch_bounds__(256)
proj_kernel(const float* __restrict__ x,
            const float* __restrict__ bq,
            const float* __restrict__ bk,
            const float* __restrict__ bv) {
    extern __shared__ float sm[];
    float* xT = sm;                   // [F][XT_PITCH]
    float* Wt = sm + F*XT_PITCH;      // [F][F]

    const int tid  = threadIdx.x;
    const int row0 = blockIdx.x * NTILE;

    // load x tile transposed: xT[f][r]
    for (int idx = tid; idx < NTILE*32; idx += TPB) {
        int r  = idx & (NTILE-1);
        int f4 = idx >> 6;            // 0..31
        float4 xv = *(const float4*)(x + (size_t)(row0 + r)*F + f4*4);
        xT[(f4*4+0)*XT_PITCH + r] = xv.x;
        xT[(f4*4+1)*XT_PITCH + r] = xv.y;
        xT[(f4*4+2)*XT_PITCH + r] = xv.z;
        xT[(f4*4+3)*XT_PITCH + r] = xv.w;
    }

    const int ty = tid >> 4, tx = tid & 15;
    const int r0 = ty * 4;
    const int cl = tx * 4;            // low  column quad
    const int ch = 64 + tx * 4;       // high column quad

    #pragma unroll 1
    for (int m = 0; m < 3; m++) {
        __syncthreads();
        const float* gwt = g_Wt[m];
        for (int idx = tid; idx < F*F; idx += TPB) Wt[idx] = gwt[idx];
        __syncthreads();

        float acc[4][8];
        #pragma unroll
        for (int a = 0; a < 4; a++)
            #pragma unroll
            for (int c = 0; c < 8; c++) acc[a][c] = 0.f;

        #pragma unroll 4
        for (int f = 0; f < F; f++) {
            float4 av = *(const float4*)(xT + f*XT_PITCH + r0);
            float4 b0 = *(const float4*)(Wt + f*F + cl);
            float4 b1 = *(const float4*)(Wt + f*F + ch);
            float aa[4] = {av.x, av.y, av.z, av.w};
            float bb[8] = {b0.x, b0.y, b0.z, b0.w, b1.x, b1.y, b1.z, b1.w};
            #pragma unroll
            for (int a = 0; a < 4; a++)
                #pragma unroll
                for (int c = 0; c < 8; c++) acc[a][c] = fmaf(aa[a], bb[c], acc[a][c]);
        }

        const float* bias = (m == 0) ? bq : ((m == 1) ? bk : bv);
        float bvv[8];
        #pragma unroll
        for (int j = 0; j < 4; j++) { bvv[j] = __ldg(bias + cl + j); bvv[4+j] = __ldg(bias + ch + j); }
        #pragma unroll
        for (int a = 0; a < 4; a++)
            #pragma unroll
            for (int c = 0; c < 8; c++) acc[a][c] += bvv[c];

        if (m < 2) {
            float* gc = (m == 0) ? g_qc : g_kc;
            float* gs = (m == 0) ? g_qs : g_ks;
            #pragma unroll
            for (int a = 0; a < 4; a++) {
                size_t rowg = (size_t)(row0 + r0 + a);
                size_t srow = (size_t)((row0 + r0 + a) & (S - 1));   // seq position (FIX: was rowg)
                float4 c0v = *(const float4*)(g_cos + srow*F + cl);
                float4 c1v = *(const float4*)(g_cos + srow*F + ch);
                float4 s0v = *(const float4*)(g_sin + srow*F + cl);
                float4 s1v = *(const float4*)(g_sin + srow*F + ch);
                float4 o;
                o.x = acc[a][0]*c0v.x; o.y = acc[a][1]*c0v.y; o.z = acc[a][2]*c0v.z; o.w = acc[a][3]*c0v.w;
                *(float4*)(gc + rowg*F + cl) = o;
                o.x = acc[a][4]*c1v.x; o.y = acc[a][5]*c1v.y; o.z = acc[a][6]*c1v.z; o.w = acc[a][7]*c1v.w;
                *(float4*)(gc + rowg*F + ch) = o;
                o.x = acc[a][0]*s0v.x; o.y = acc[a][1]*s0v.y; o.z = acc[a][2]*s0v.z; o.w = acc[a][3]*s0v.w;
                *(float4*)(gs + rowg*F + cl) = o;
                o.x = acc[a][4]*s1v.x; o.y = acc[a][5]*s1v.y; o.z = acc[a][6]*s1v.z; o.w = acc[a][7]*s1v.w;
                *(float4*)(gs + rowg*F + ch) = o;
            }
        } else {
            #pragma unroll
            for (int a = 0; a < 4; a++) {
                size_t rowg = (size_t)(row0 + r0 + a);
                float4 o;
                o.x = acc[a][0]; o.y = acc[a][1]; o.z = acc[a][2]; o.w = acc[a][3];
                *(float4*)(g_v + rowg*F + cl) = o;
                o.x = acc[a][4]; o.y = acc[a][5]; o.z = acc[a][6]; o.w = acc[a][7];
                *(float4*)(g_v + rowg*F + ch) = o;
            }
        }
    }
}

// ---------------- banded retention attention ----------------
// block = (batch, 64-query tile); loops over <=9 key tiles within decay band
__global__ void __launch_bounds__(256)
attn_kernel(float* __restrict__ out) {
    extern __shared__ float sm[];
    float* qcT = sm;                          // [F][QPITCH]
    float* qsT = qcT + F*QPITCH;
    float* kcT = qsT + F*QPITCH;
    float* ksT = kcT + F*QPITCH;
    float* vs  = ksT + F*QPITCH;              // [NTILE][VPITCH]
    float* sc  = vs  + NTILE*VPITCH;          // [NTILE][SPITCH]
    float* dec = sc  + NTILE*SPITCH;          // 640

    const int tid = threadIdx.x;
    const int b   = blockIdx.x >> 6;
    const int i   = blockIdx.x & 63;
    const size_t qrow0 = (size_t)(b*S + i*NTILE);

    for (int e = tid; e < 640; e += TPB) dec[e] = g_decay[e];

    // load q tiles transposed
    for (int idx = tid; idx < NTILE*32; idx += TPB) {
        int r  = idx & 63;
        int f4 = idx >> 6;
        float4 a = *(const float4*)(g_qc + (qrow0 + r)*F + f4*4);
        float4 c = *(const float4*)(g_qs + (qrow0 + r)*F + f4*4);
        qcT[(f4*4+0)*QPITCH + r] = a.x; qcT[(f4*4+1)*QPITCH + r] = a.y;
        qcT[(f4*4+2)*QPITCH + r] = a.z; qcT[(f4*4+3)*QPITCH + r] = a.w;
        qsT[(f4*4+0)*QPITCH + r] = c.x; qsT[(f4*4+1)*QPITCH + r] = c.y;
        qsT[(f4*4+2)*QPITCH + r] = c.z; qsT[(f4*4+3)*QPITCH + r] = c.w;
    }

    const int ty = tid >> 4, tx = tid & 15;
    const int r0 = ty * 4;
    const int t0 = tx * 4;
    const int cl = tx * 4;
    const int ch = 64 + tx * 4;

    float acc_o[4][8];
    #pragma unroll
    for (int a = 0; a < 4; a++)
        #pragma unroll
        for (int c = 0; c < 8; c++) acc_o[a][c] = 0.f;

    const int jmin = (i > MAXDJ) ? (i - MAXDJ) : 0;
    for (int j = i; j >= jmin; j--) {
        __syncthreads();   // previous iteration done with kcT/ksT/vs/sc
        const size_t krow0 = (size_t)(b*S + j*NTILE);
        for (int idx = tid; idx < NTILE*32; idx += TPB) {
            int r  = idx & 63;
            int f4 = idx >> 6;
            float4 a = *(const float4*)(g_kc + (krow0 + r)*F + f4*4);
            float4 c = *(const float4*)(g_ks + (krow0 + r)*F + f4*4);
            kcT[(f4*4+0)*QPITCH + r] = a.x; kcT[(f4*4+1)*QPITCH + r] = a.y;
            kcT[(f4*4+2)*QPITCH + r] = a.z; kcT[(f4*4+3)*QPITCH + r] = a.w;
            ksT[(f4*4+0)*QPITCH + r] = c.x; ksT[(f4*4+1)*QPITCH + r] = c.y;
            ksT[(f4*4+2)*QPITCH + r] = c.z; ksT[(f4*4+3)*QPITCH + r] = c.w;
            int t  = idx >> 5;
            int cq = idx & 31;
            float4 vv = *(const float4*)(g_v + (krow0 + t)*F + cq*4);
            *(float4*)(vs + t*VPITCH + cq*4) = vv;
        }
        __syncthreads();

        // phase 1: score tile = qc.kc^T + qs.ks^T, then decay
        float a_s[4][4];
        #pragma unroll
        for (int a = 0; a < 4; a++)
            #pragma unroll
            for (int c = 0; c < 4; c++) a_s[a][c] = 0.f;

        #pragma unroll 4
        for (int f = 0; f < F; f++) {
            float4 qa = *(const float4*)(qcT + f*QPITCH + r0);
            float4 kb = *(const float4*)(kcT + f*QPITCH + t0);
            float qv[4] = {qa.x, qa.y, qa.z, qa.w};
            float kv[4] = {kb.x, kb.y, kb.z, kb.w};
            #pragma unroll
            for (int a = 0; a < 4; a++)
                #pragma unroll
                for (int c = 0; c < 4; c++) a_s[a][c] = fmaf(qv[a], kv[c], a_s[a][c]);
        }
        #pragma unroll 4
        for (int f = 0; f < F; f++) {
            float4 qa = *(const float4*)(qsT + f*QPITCH + r0);
            float4 kb = *(const float4*)(ksT + f*QPITCH + t0);
            float qv[4] = {qa.x, qa.y, qa.z, qa.w};
            float kv[4] = {kb.x, kb.y, kb.z, kb.w};
            #pragma unroll
            for (int a = 0; a < 4; a++)
                #pragma unroll
                for (int c = 0; c < 4; c++) a_s[a][c] = fmaf(qv[a], kv[c], a_s[a][c]);
        }

        const int dj64 = (i - j) * 64;
        #pragma unroll
        for (int a = 0; a < 4; a++)
            #pragma unroll
            for (int c = 0; c < 4; c++) {
                int e = dj64 + (r0 + a) - (t0 + c);
                float d = (e >= 0) ? dec[e] : 0.f;
                sc[(r0 + a)*SPITCH + (t0 + c)] = a_s[a][c] * d;
            }
        __syncthreads();

        // phase 2: acc_o += score_tile @ v_tile
        #pragma unroll 4
        for (int t = 0; t < NTILE; t++) {
            float sv[4];
            #pragma unroll
            for (int a = 0; a < 4; a++) sv[a] = sc[(r0 + a)*SPITCH + t];
            float4 v0 = *(const float4*)(vs + t*VPITCH + cl);
            float4 v1 = *(const float4*)(vs + t*VPITCH + ch);
            float vv[8] = {v0.x, v0.y, v0.z, v0.w, v1.x, v1.y, v1.z, v1.w};
            #pragma unroll
            for (int a = 0; a < 4; a++)
                #pragma unroll
                for (int c = 0; c < 8; c++) acc_o[a][c] = fmaf(sv[a], vv[c], acc_o[a][c]);
        }
    }

    // write output
    #pragma unroll
    for (int a = 0; a < 4; a++) {
        size_t rowg = qrow0 + r0 + a;
        float4 o;
        o.x = acc_o[a][0]; o.y = acc_o[a][1]; o.z = acc_o[a][2]; o.w = acc_o[a][3];
        *(float4*)(out + rowg*F + cl) = o;
        o.x = acc_o[a][4]; o.y = acc_o[a][5]; o.z = acc_o[a][6]; o.w = acc_o[a][7];
        *(float4*)(out + rowg*F + ch) = o;
    }
}

// ---------------- launch ----------------
extern "C" void kernel_launch(void* const* d_in, const int* in_sizes, int n_in,
                              void* d_out, int out_size) {
    const float* x  = (const float*)d_in[0];
    const float* Wq = (const float*)d_in[1];
    const float* bq = (const float*)d_in[2];
    const float* Wk = (const float*)d_in[3];
    const float* bk = (const float*)d_in[4];
    const float* Wv = (const float*)d_in[5];
    const float* bv = (const float*)d_in[6];
    const float* th = (const float*)d_in[7];
    float* out = (float*)d_out;

    const size_t PROJ_SMEM = (size_t)(F*XT_PITCH + F*F) * sizeof(float);                  // 100,352 B
    const size_t ATT_SMEM  = (size_t)(4*F*QPITCH + NTILE*VPITCH + NTILE*SPITCH + 640) * sizeof(float); // 192,256 B

    cudaFuncSetAttribute(proj_kernel, cudaFuncAttributeMaxDynamicSharedMemorySize, (int)PROJ_SMEM);
    cudaFuncSetAttribute(attn_kernel, cudaFuncAttributeMaxDynamicSharedMemorySize, (int)ATT_SMEM);

    init_tables<<<S + 8, F>>>(th);
    transpose_w<<<3, 256>>>(Wq, Wk, Wv);
    proj_kernel<<<NQTILES, TPB, PROJ_SMEM>>>(x, bq, bk, bv);
    attn_kernel<<<NQTILES, TPB, ATT_SMEM>>>(out);
}

// round 6
// speedup vs baseline: 2.3068x; 2.3068x over previous
#include <cuda_runtime.h>
#include <math.h>
#include <stdint.h>

#define B 4
#define S 4096
#define F 128
#define GAMMA 0.96875f
#define NTILE 64
#define TPB 256
#define NQTILES ((B*S)/NTILE)   // 256
#define MAXDJ 8                 // gamma^513 ~ 8.6e-8 << 1e-3 tolerance

#define XT_PITCH 68

// smem float offsets for attention kernel
#define QK_PITCH 260   // 260 % 32 == 4 -> A/B frag loads conflict-free
#define V_PITCH  136   // 136 % 32 == 8 -> B frag loads conflict-free
#define S_PITCH  68    // 68  % 32 == 4
#define OFF_Q2   0
#define OFF_K2   (OFF_Q2 + 64*QK_PITCH)      // 16640
#define OFF_V    (OFF_K2 + 64*QK_PITCH)      // 33280
#define OFF_S2   (OFF_V  + 64*V_PITCH)       // 41984
#define OFF_DEC  (OFF_S2 + 64*S_PITCH)       // 46336
#define ATT_SMEM_FLOATS (OFF_DEC + 640)      // 46976 floats = 187,904 B

// ---------------- scratch ----------------
__device__ __align__(16) float g_cos[S*F];
__device__ __align__(16) float g_sin[S*F];
__device__ __align__(16) float g_Wt[3][F*F];
__device__ __align__(16) float g_qc[B*S*F];
__device__ __align__(16) float g_qs[B*S*F];
__device__ __align__(16) float g_kc[B*S*F];
__device__ __align__(16) float g_ks[B*S*F];
__device__ __align__(16) float g_v [B*S*F];

// ---------------- helpers ----------------
__device__ __forceinline__ uint32_t f2tf32(float f) {
    uint32_t r; asm("cvt.rna.tf32.f32 %0, %1;" : "=r"(r) : "f"(f)); return r;
}
__device__ __forceinline__ void mma_tf32(float c[4],
                                         uint32_t a0, uint32_t a1, uint32_t a2, uint32_t a3,
                                         uint32_t b0, uint32_t b1) {
    asm volatile("mma.sync.aligned.m16n8k8.row.col.f32.tf32.tf32.f32 "
                 "{%0,%1,%2,%3}, {%4,%5,%6,%7}, {%8,%9}, {%0,%1,%2,%3};"
                 : "+f"(c[0]), "+f"(c[1]), "+f"(c[2]), "+f"(c[3])
                 : "r"(a0), "r"(a1), "r"(a2), "r"(a3), "r"(b0), "r"(b1));
}

// ---------------- init: cos/sin tables ----------------
__global__ void init_tables(const float* __restrict__ theta) {
    int bx = blockIdx.x, t = threadIdx.x;
    float mt = (float)(bx + 1) * theta[t];
    float sn, cs;
    sincosf(mt, &sn, &cs);
    g_cos[bx*F + t] = cs;
    g_sin[bx*F + t] = sn;
}

// ---------------- transpose weights ----------------
__global__ void transpose_w(const float* __restrict__ Wq,
                            const float* __restrict__ Wk,
                            const float* __restrict__ Wv) {
    const float* W = (blockIdx.x == 0) ? Wq : ((blockIdx.x == 1) ? Wk : Wv);
    float* Wt = g_Wt[blockIdx.x];
    for (int idx = threadIdx.x; idx < F*F; idx += blockDim.x) {
        int c = idx & (F-1);
        int f = idx >> 7;
        Wt[idx] = W[c*F + f];
    }
}

// ---------------- fused QKV projection + cos/sin modulation (SIMT fp32) ----------------
__global__ void __launch_bounds__(256)
proj_kernel(const float* __restrict__ x,
            const float* __restrict__ bq,
            const float* __restrict__ bk,
            const float* __restrict__ bv) {
    extern __shared__ float sm[];
    float* xT = sm;                   // [F][XT_PITCH]
    float* Wt = sm + F*XT_PITCH;      // [F][F]

    const int tid  = threadIdx.x;
    const int row0 = blockIdx.x * NTILE;

    for (int idx = tid; idx < NTILE*32; idx += TPB) {
        int r  = idx & (NTILE-1);
        int f4 = idx >> 6;
        float4 xv = *(const float4*)(x + (size_t)(row0 + r)*F + f4*4);
        xT[(f4*4+0)*XT_PITCH + r] = xv.x;
        xT[(f4*4+1)*XT_PITCH + r] = xv.y;
        xT[(f4*4+2)*XT_PITCH + r] = xv.z;
        xT[(f4*4+3)*XT_PITCH + r] = xv.w;
    }

    const int ty = tid >> 4, tx = tid & 15;
    const int r0 = ty * 4;
    const int cl = tx * 4;
    const int ch = 64 + tx * 4;

    #pragma unroll 1
    for (int m = 0; m < 3; m++) {
        __syncthreads();
        const float* gwt = g_Wt[m];
        for (int idx = tid; idx < F*F; idx += TPB) Wt[idx] = gwt[idx];
        __syncthreads();

        float acc[4][8];
        #pragma unroll
        for (int a = 0; a < 4; a++)
            #pragma unroll
            for (int c = 0; c < 8; c++) acc[a][c] = 0.f;

        #pragma unroll 4
        for (int f = 0; f < F; f++) {
            float4 av = *(const float4*)(xT + f*XT_PITCH + r0);
            float4 b0 = *(const float4*)(Wt + f*F + cl);
            float4 b1 = *(const float4*)(Wt + f*F + ch);
            float aa[4] = {av.x, av.y, av.z, av.w};
            float bb[8] = {b0.x, b0.y, b0.z, b0.w, b1.x, b1.y, b1.z, b1.w};
            #pragma unroll
            for (int a = 0; a < 4; a++)
                #pragma unroll
                for (int c = 0; c < 8; c++) acc[a][c] = fmaf(aa[a], bb[c], acc[a][c]);
        }

        const float* bias = (m == 0) ? bq : ((m == 1) ? bk : bv);
        float bvv[8];
        #pragma unroll
        for (int j = 0; j < 4; j++) { bvv[j] = __ldg(bias + cl + j); bvv[4+j] = __ldg(bias + ch + j); }
        #pragma unroll
        for (int a = 0; a < 4; a++)
            #pragma unroll
            for (int c = 0; c < 8; c++) acc[a][c] += bvv[c];

        if (m < 2) {
            float* gc = (m == 0) ? g_qc : g_kc;
            float* gs = (m == 0) ? g_qs : g_ks;
            #pragma unroll
            for (int a = 0; a < 4; a++) {
                size_t rowg = (size_t)(row0 + r0 + a);
                size_t srow = (size_t)((row0 + r0 + a) & (S - 1));
                float4 c0v = *(const float4*)(g_cos + srow*F + cl);
                float4 c1v = *(const float4*)(g_cos + srow*F + ch);
                float4 s0v = *(const float4*)(g_sin + srow*F + cl);
                float4 s1v = *(const float4*)(g_sin + srow*F + ch);
                float4 o;
                o.x = acc[a][0]*c0v.x; o.y = acc[a][1]*c0v.y; o.z = acc[a][2]*c0v.z; o.w = acc[a][3]*c0v.w;
                *(float4*)(gc + rowg*F + cl) = o;
                o.x = acc[a][4]*c1v.x; o.y = acc[a][5]*c1v.y; o.z = acc[a][6]*c1v.z; o.w = acc[a][7]*c1v.w;
                *(float4*)(gc + rowg*F + ch) = o;
                o.x = acc[a][0]*s0v.x; o.y = acc[a][1]*s0v.y; o.z = acc[a][2]*s0v.z; o.w = acc[a][3]*s0v.w;
                *(float4*)(gs + rowg*F + cl) = o;
                o.x = acc[a][4]*s1v.x; o.y = acc[a][5]*s1v.y; o.z = acc[a][6]*s1v.z; o.w = acc[a][7]*s1v.w;
                *(float4*)(gs + rowg*F + ch) = o;
            }
        } else {
            #pragma unroll
            for (int a = 0; a < 4; a++) {
                size_t rowg = (size_t)(row0 + r0 + a);
                float4 o;
                o.x = acc[a][0]; o.y = acc[a][1]; o.z = acc[a][2]; o.w = acc[a][3];
                *(float4*)(g_v + rowg*F + cl) = o;
                o.x = acc[a][4]; o.y = acc[a][5]; o.z = acc[a][6]; o.w = acc[a][7];
                *(float4*)(g_v + rowg*F + ch) = o;
            }
        }
    }
}

// ================= banded attention via mma.sync tf32 =================
// CTA = (batch, 64-row query tile); 8 warps: 4 row-groups x 2 col-groups.
// Score: S[64x64] = [Qc|Qs][64x256] @ [Kc|Ks]^T. Warp tile 16x32, K=256.
// O[64x128] += S @ V. Warp tile 16x64, K=64. O accumulated in registers.
__global__ void __launch_bounds__(256)
attn_mma_kernel(float* __restrict__ out) {
    extern __shared__ float sm[];
    float* Q2  = sm + OFF_Q2;    // [64][QK_PITCH], cols 0..255 = qc|qs (tf32 bits)
    float* K2  = sm + OFF_K2;    // [64][QK_PITCH]
    float* Vs  = sm + OFF_V;     // [64][V_PITCH]
    float* S2  = sm + OFF_S2;    // [64][S_PITCH]
    float* dec = sm + OFF_DEC;   // [640]

    const int tid = threadIdx.x;
    const int b   = blockIdx.x >> 6;
    const int i   = blockIdx.x & 63;
    const size_t qrow0 = (size_t)b * S + (size_t)i * 64;
    const float L = log2f(GAMMA);

    // decay table
    for (int e = tid; e < 640; e += TPB) dec[e] = exp2f((float)e * L);

    // Q2 fill (tf32-rounded)
    for (int idx = tid; idx < 64*32; idx += TPB) {
        int r  = idx >> 5;
        int k4 = (idx & 31) << 2;
        float4 a = *(const float4*)(g_qc + (qrow0 + r)*F + k4);
        uint4 ua = { f2tf32(a.x), f2tf32(a.y), f2tf32(a.z), f2tf32(a.w) };
        *(uint4*)(Q2 + r*QK_PITCH + k4) = ua;
        float4 s = *(const float4*)(g_qs + (qrow0 + r)*F + k4);
        uint4 us = { f2tf32(s.x), f2tf32(s.y), f2tf32(s.z), f2tf32(s.w) };
        *(uint4*)(Q2 + r*QK_PITCH + 128 + k4) = us;
    }

    const int w    = tid >> 5;
    const int lane = tid & 31;
    const int g    = lane >> 2;      // group id 0..7
    const int ti   = lane & 3;       // thread-in-group 0..3
    const int rw   = (w & 3) * 16;   // warp row base
    const int cw   = (w >> 2);       // warp col group 0/1

    float oc[8][4];
    #pragma unroll
    for (int jn = 0; jn < 8; jn++)
        #pragma unroll
        for (int q = 0; q < 4; q++) oc[jn][q] = 0.f;

    const int jmin = (i > MAXDJ) ? (i - MAXDJ) : 0;
    for (int j = i; j >= jmin; j--) {
        __syncthreads();   // prev-iteration consumers done with K2/Vs
        const size_t krow0 = (size_t)b * S + (size_t)j * 64;

        // fill K2 = kc|ks, Vs = v (both tf32-rounded)
        for (int idx = tid; idx < 64*32; idx += TPB) {
            int r  = idx >> 5;
            int k4 = (idx & 31) << 2;
            float4 a = *(const float4*)(g_kc + (krow0 + r)*F + k4);
            uint4 ua = { f2tf32(a.x), f2tf32(a.y), f2tf32(a.z), f2tf32(a.w) };
            *(uint4*)(K2 + r*QK_PITCH + k4) = ua;
            float4 s = *(const float4*)(g_ks + (krow0 + r)*F + k4);
            uint4 us = { f2tf32(s.x), f2tf32(s.y), f2tf32(s.z), f2tf32(s.w) };
            *(uint4*)(K2 + r*QK_PITCH + 128 + k4) = us;
            float4 v = *(const float4*)(g_v + (krow0 + r)*F + k4);
            uint4 uv = { f2tf32(v.x), f2tf32(v.y), f2tf32(v.z), f2tf32(v.w) };
            *(uint4*)(Vs + r*V_PITCH + k4) = uv;
        }
        __syncthreads();

        // ---- score GEMM: warp tile 16x32, K=256 ----
        float sc[4][4];
        #pragma unroll
        for (int jn = 0; jn < 4; jn++)
            #pragma unroll
            for (int q = 0; q < 4; q++) sc[jn][q] = 0.f;

        const uint32_t* Q2u = (const uint32_t*)Q2;
        const uint32_t* K2u = (const uint32_t*)K2;
        #pragma unroll 4
        for (int kk = 0; kk < 32; kk++) {
            const int kb = kk * 8;
            uint32_t a0 = Q2u[(rw + g    )*QK_PITCH + kb + ti    ];
            uint32_t a1 = Q2u[(rw + g + 8)*QK_PITCH + kb + ti    ];
            uint32_t a2 = Q2u[(rw + g    )*QK_PITCH + kb + ti + 4];
            uint32_t a3 = Q2u[(rw + g + 8)*QK_PITCH + kb + ti + 4];
            #pragma unroll
            for (int jn = 0; jn < 4; jn++) {
                const int nrow = cw*32 + jn*8 + g;
                uint32_t b0 = K2u[nrow*QK_PITCH + kb + ti    ];
                uint32_t b1 = K2u[nrow*QK_PITCH + kb + ti + 4];
                mma_tf32(sc[jn], a0, a1, a2, a3, b0, b1);
            }
        }

        // ---- epilogue: decay + causal mask, tf32 round, store to S2 ----
        {
            const int dj = (i - j) * 64;
            uint32_t* S2u = (uint32_t*)S2;
            #pragma unroll
            for (int jn = 0; jn < 4; jn++) {
                const int col = cw*32 + jn*8 + 2*ti;
                const int rm0 = rw + g, rm1 = rw + g + 8;
                int e00 = dj + rm0 - col;
                int e01 = e00 - 1;
                int e10 = dj + rm1 - col;
                int e11 = e10 - 1;
                float d00 = (e00 >= 0) ? dec[e00] : 0.f;
                float d01 = (e01 >= 0) ? dec[e01] : 0.f;
                float d10 = (e10 >= 0) ? dec[e10] : 0.f;
                float d11 = (e11 >= 0) ? dec[e11] : 0.f;
                S2u[rm0*S_PITCH + col    ] = f2tf32(sc[jn][0] * d00);
                S2u[rm0*S_PITCH + col + 1] = f2tf32(sc[jn][1] * d01);
                S2u[rm1*S_PITCH + col    ] = f2tf32(sc[jn][2] * d10);
                S2u[rm1*S_PITCH + col + 1] = f2tf32(sc[jn][3] * d11);
            }
        }
        __syncthreads();

        // ---- O += S @ V: warp tile 16x64, K=64 ----
        const uint32_t* S2u = (const uint32_t*)S2;
        const uint32_t* Vsu = (const uint32_t*)Vs;
        #pragma unroll
        for (int kk = 0; kk < 8; kk++) {
            const int kb = kk * 8;
            uint32_t a0 = S2u[(rw + g    )*S_PITCH + kb + ti    ];
            uint32_t a1 = S2u[(rw + g + 8)*S_PITCH + kb + ti    ];
            uint32_t a2 = S2u[(rw + g    )*S_PITCH + kb + ti + 4];
            uint32_t a3 = S2u[(rw + g + 8)*S_PITCH + kb + ti + 4];
            #pragma unroll
            for (int jn = 0; jn < 8; jn++) {
                const int nc = cw*64 + jn*8 + g;
                uint32_t b0 = Vsu[(kb + ti    )*V_PITCH + nc];
                uint32_t b1 = Vsu[(kb + ti + 4)*V_PITCH + nc];
                mma_tf32(oc[jn], a0, a1, a2, a3, b0, b1);
            }
        }
    }

    // write O
    {
        const size_t row0 = qrow0 + rw + g;
        const size_t row1 = row0 + 8;
        #pragma unroll
        for (int jn = 0; jn < 8; jn++) {
            const int col = cw*64 + jn*8 + 2*ti;
            *(float2*)(out + row0*F + col) = make_float2(oc[jn][0], oc[jn][1]);
            *(float2*)(out + row1*F + col) = make_float2(oc[jn][2], oc[jn][3]);
        }
    }
}

// ---------------- launch ----------------
extern "C" void kernel_launch(void* const* d_in, const int* in_sizes, int n_in,
                              void* d_out, int out_size) {
    const float* x  = (const float*)d_in[0];
    const float* Wq = (const float*)d_in[1];
    const float* bq = (const float*)d_in[2];
    const float* Wk = (const float*)d_in[3];
    const float* bk = (const float*)d_in[4];
    const float* Wv = (const float*)d_in[5];
    const float* bv = (const float*)d_in[6];
    const float* th = (const float*)d_in[7];
    float* out = (float*)d_out;

    const size_t PROJ_SMEM = (size_t)(F*XT_PITCH + F*F) * sizeof(float);
    const size_t ATT_SMEM  = (size_t)ATT_SMEM_FLOATS * sizeof(float);   // 187,904 B

    cudaFuncSetAttribute(proj_kernel, cudaFuncAttributeMaxDynamicSharedMemorySize, (int)PROJ_SMEM);
    cudaFuncSetAttribute(attn_mma_kernel, cudaFuncAttributeMaxDynamicSharedMemorySize, (int)ATT_SMEM);

    init_tables<<<S, F>>>(th);
    transpose_w<<<3, 256>>>(Wq, Wk, Wv);
    proj_kernel<<<NQTILES, TPB, PROJ_SMEM>>>(x, bq, bk, bv);
    attn_mma_kernel<<<NQTILES, TPB, ATT_SMEM>>>(out);
}

// round 7
// speedup vs baseline: 2.8672x; 1.2429x over previous
#include <cuda_runtime.h>
#include <math.h>
#include <stdint.h>

#define B 4
#define S 4096
#define F 128
#define GAMMA 0.96875f
#define NTILE 64
#define TPB 256
#define NQTILES ((B*S)/NTILE)   // 256
#define MAXDJ 8                 // gamma^513 ~ 8.6e-8 << 1e-3 tolerance

// proj smem layout (floats)
#define XP 132                  // x tile pitch; 132%32==4 -> conflict-free frags
#define WP 132
#define PROJ_SMEM_FLOATS (64*XP + 128*WP)   // 25344 floats = 101,376 B -> 2 CTAs/SM

// attention smem layout (floats)
#define QK_PITCH 260   // 260 % 32 == 4 -> A/B frag loads conflict-free
#define V_PITCH  136   // 136 % 32 == 8 -> B frag loads conflict-free
#define S_PITCH  68    // 68  % 32 == 4
#define OFF_Q2   0
#define OFF_K2   (OFF_Q2 + 64*QK_PITCH)
#define OFF_V    (OFF_K2 + 64*QK_PITCH)
#define OFF_S2   (OFF_V  + 64*V_PITCH)
#define OFF_DEC  (OFF_S2 + 64*S_PITCH)
#define ATT_SMEM_FLOATS (OFF_DEC + 640)      // 187,904 B

// ---------------- scratch ----------------
__device__ __align__(16) float g_cos[S*F];
__device__ __align__(16) float g_sin[S*F];
__device__ __align__(16) float g_qc[B*S*F];
__device__ __align__(16) float g_qs[B*S*F];
__device__ __align__(16) float g_kc[B*S*F];
__device__ __align__(16) float g_ks[B*S*F];
__device__ __align__(16) float g_v [B*S*F];

// ---------------- helpers ----------------
__device__ __forceinline__ uint32_t f2tf32(float f) {
    uint32_t r; asm("cvt.rna.tf32.f32 %0, %1;" : "=r"(r) : "f"(f)); return r;
}
__device__ __forceinline__ void mma_tf32(float c[4],
                                         uint32_t a0, uint32_t a1, uint32_t a2, uint32_t a3,
                                         uint32_t b0, uint32_t b1) {
    asm volatile("mma.sync.aligned.m16n8k8.row.col.f32.tf32.tf32.f32 "
                 "{%0,%1,%2,%3}, {%4,%5,%6,%7}, {%8,%9}, {%0,%1,%2,%3};"
                 : "+f"(c[0]), "+f"(c[1]), "+f"(c[2]), "+f"(c[3])
                 : "r"(a0), "r"(a1), "r"(a2), "r"(a3), "r"(b0), "r"(b1));
}

// ---------------- init: cos/sin tables ----------------
__global__ void init_tables(const float* __restrict__ theta) {
    int bx = blockIdx.x, t = threadIdx.x;
    float mt = (float)(bx + 1) * theta[t];
    float sn, cs;
    sincosf(mt, &sn, &cs);
    g_cos[bx*F + t] = cs;
    g_sin[bx*F + t] = sn;
}

// ---------------- QKV projection via mma.sync tf32 ----------------
// CTA = 64 rows x 128 cols, K=128; loops m over {q,k,v}. 8 warps, warp tile 32x32.
// B operand B[n][k] == W[n][k] (original row-major W) -> no transpose needed.
__global__ void __launch_bounds__(256)
proj_mma_kernel(const float* __restrict__ x,
                const float* __restrict__ Wq, const float* __restrict__ bq,
                const float* __restrict__ Wk, const float* __restrict__ bk,
                const float* __restrict__ Wv, const float* __restrict__ bv) {
    extern __shared__ float sm[];
    float* xs = sm;               // [64][XP]
    float* Ws = sm + 64*XP;       // [128][WP]
    uint32_t* xsu = (uint32_t*)xs;
    uint32_t* Wsu = (uint32_t*)Ws;

    const int tid  = threadIdx.x;
    const int row0 = blockIdx.x * 64;

    // fill x tile (tf32-rounded)
    for (int idx = tid; idx < 64*32; idx += TPB) {
        int r  = idx >> 5;
        int c4 = (idx & 31) << 2;
        float4 xv = *(const float4*)(x + (size_t)(row0 + r)*F + c4);
        uint4 ux = { f2tf32(xv.x), f2tf32(xv.y), f2tf32(xv.z), f2tf32(xv.w) };
        *(uint4*)(xs + r*XP + c4) = ux;
    }

    const int w    = tid >> 5;
    const int lane = tid & 31;
    const int g    = lane >> 2;
    const int ti   = lane & 3;
    const int rw   = (w & 1) * 32;        // warp row base within 64
    const int cwb  = (w >> 1) * 32;       // warp col base within 128

    #pragma unroll 1
    for (int m = 0; m < 3; m++) {
        const float* Wm   = (m == 0) ? Wq : ((m == 1) ? Wk : Wv);
        const float* bias = (m == 0) ? bq : ((m == 1) ? bk : bv);

        __syncthreads();   // prev iteration done with Ws
        for (int idx = tid; idx < 128*32; idx += TPB) {
            int r  = idx >> 5;
            int c4 = (idx & 31) << 2;
            float4 wv = *(const float4*)(Wm + (size_t)r*F + c4);
            uint4 uw = { f2tf32(wv.x), f2tf32(wv.y), f2tf32(wv.z), f2tf32(wv.w) };
            *(uint4*)(Ws + r*WP + c4) = uw;
        }
        __syncthreads();

        float acc[2][4][4];
        #pragma unroll
        for (int rb = 0; rb < 2; rb++)
            #pragma unroll
            for (int jn = 0; jn < 4; jn++)
                #pragma unroll
                for (int q = 0; q < 4; q++) acc[rb][jn][q] = 0.f;

        #pragma unroll 4
        for (int kk = 0; kk < 16; kk++) {
            const int kb = kk * 8;
            uint32_t a[2][4];
            #pragma unroll
            for (int rb = 0; rb < 2; rb++) {
                const int rr = rw + rb*16;
                a[rb][0] = xsu[(rr + g    )*XP + kb + ti    ];
                a[rb][1] = xsu[(rr + g + 8)*XP + kb + ti    ];
                a[rb][2] = xsu[(rr + g    )*XP + kb + ti + 4];
                a[rb][3] = xsu[(rr + g + 8)*XP + kb + ti + 4];
            }
            #pragma unroll
            for (int jn = 0; jn < 4; jn++) {
                const int nr = cwb + jn*8 + g;
                uint32_t b0 = Wsu[nr*WP + kb + ti    ];
                uint32_t b1 = Wsu[nr*WP + kb + ti + 4];
                mma_tf32(acc[0][jn], a[0][0], a[0][1], a[0][2], a[0][3], b0, b1);
                mma_tf32(acc[1][jn], a[1][0], a[1][1], a[1][2], a[1][3], b0, b1);
            }
        }

        // epilogue: bias (+ cos/sin modulation for q,k), float2 stores
        float* gc = (m == 0) ? g_qc : g_kc;
        float* gs = (m == 0) ? g_qs : g_ks;
        #pragma unroll
        for (int jn = 0; jn < 4; jn++) {
            const int col = cwb + jn*8 + 2*ti;
            const float2 bb = *(const float2*)(bias + col);
            #pragma unroll
            for (int rb = 0; rb < 2; rb++) {
                #pragma unroll
                for (int h = 0; h < 2; h++) {
                    const int rowg = row0 + rw + rb*16 + g + 8*h;
                    const int srow = rowg & (S - 1);
                    float c0 = acc[rb][jn][2*h    ] + bb.x;
                    float c1 = acc[rb][jn][2*h + 1] + bb.y;
                    if (m < 2) {
                        float2 cv = *(const float2*)(g_cos + (size_t)srow*F + col);
                        float2 sv = *(const float2*)(g_sin + (size_t)srow*F + col);
                        *(float2*)(gc + (size_t)rowg*F + col) = make_float2(c0*cv.x, c1*cv.y);
                        *(float2*)(gs + (size_t)rowg*F + col) = make_float2(c0*sv.x, c1*sv.y);
                    } else {
                        *(float2*)(g_v + (size_t)rowg*F + col) = make_float2(c0, c1);
                    }
                }
            }
        }
    }
}

// ================= banded attention via mma.sync tf32 =================
__global__ void __launch_bounds__(256)
attn_mma_kernel(float* __restrict__ out) {
    extern __shared__ float sm[];
    float* Q2  = sm + OFF_Q2;
    float* K2  = sm + OFF_K2;
    float* Vs  = sm + OFF_V;
    float* S2  = sm + OFF_S2;
    float* dec = sm + OFF_DEC;

    const int tid = threadIdx.x;
    // heavy-tile-first mapping: i descends with blockIdx so 9-chunk tiles fill wave 1
    const int i   = 63 - (blockIdx.x >> 2);
    const int b   = blockIdx.x & 3;
    const size_t qrow0 = (size_t)b * S + (size_t)i * 64;
    const float L = log2f(GAMMA);

    for (int e = tid; e < 640; e += TPB) dec[e] = exp2f((float)e * L);

    for (int idx = tid; idx < 64*32; idx += TPB) {
        int r  = idx >> 5;
        int k4 = (idx & 31) << 2;
        float4 a = *(const float4*)(g_qc + (qrow0 + r)*F + k4);
        uint4 ua = { f2tf32(a.x), f2tf32(a.y), f2tf32(a.z), f2tf32(a.w) };
        *(uint4*)(Q2 + r*QK_PITCH + k4) = ua;
        float4 s = *(const float4*)(g_qs + (qrow0 + r)*F + k4);
        uint4 us = { f2tf32(s.x), f2tf32(s.y), f2tf32(s.z), f2tf32(s.w) };
        *(uint4*)(Q2 + r*QK_PITCH + 128 + k4) = us;
    }

    const int w    = tid >> 5;
    const int lane = tid & 31;
    const int g    = lane >> 2;
    const int ti   = lane & 3;
    const int rw   = (w & 3) * 16;
    const int cw   = (w >> 2);

    float oc[8][4];
    #pragma unroll
    for (int jn = 0; jn < 8; jn++)
        #pragma unroll
        for (int q = 0; q < 4; q++) oc[jn][q] = 0.f;

    const int jmin = (i > MAXDJ) ? (i - MAXDJ) : 0;
    for (int j = i; j >= jmin; j--) {
        __syncthreads();
        const size_t krow0 = (size_t)b * S + (size_t)j * 64;

        for (int idx = tid; idx < 64*32; idx += TPB) {
            int r  = idx >> 5;
            int k4 = (idx & 31) << 2;
            float4 a = *(const float4*)(g_kc + (krow0 + r)*F + k4);
            uint4 ua = { f2tf32(a.x), f2tf32(a.y), f2tf32(a.z), f2tf32(a.w) };
            *(uint4*)(K2 + r*QK_PITCH + k4) = ua;
            float4 s = *(const float4*)(g_ks + (krow0 + r)*F + k4);
            uint4 us = { f2tf32(s.x), f2tf32(s.y), f2tf32(s.z), f2tf32(s.w) };
            *(uint4*)(K2 + r*QK_PITCH + 128 + k4) = us;
            float4 v = *(const float4*)(g_v + (krow0 + r)*F + k4);
            uint4 uv = { f2tf32(v.x), f2tf32(v.y), f2tf32(v.z), f2tf32(v.w) };
            *(uint4*)(Vs + r*V_PITCH + k4) = uv;
        }
        __syncthreads();

        // ---- score GEMM: warp tile 16x32, K=256 ----
        float sc[4][4];
        #pragma unroll
        for (int jn = 0; jn < 4; jn++)
            #pragma unroll
            for (int q = 0; q < 4; q++) sc[jn][q] = 0.f;

        const uint32_t* Q2u = (const uint32_t*)Q2;
        const uint32_t* K2u = (const uint32_t*)K2;
        #pragma unroll 8
        for (int kk = 0; kk < 32; kk++) {
            const int kb = kk * 8;
            uint32_t a0 = Q2u[(rw + g    )*QK_PITCH + kb + ti    ];
            uint32_t a1 = Q2u[(rw + g + 8)*QK_PITCH + kb + ti    ];
            uint32_t a2 = Q2u[(rw + g    )*QK_PITCH + kb + ti + 4];
            uint32_t a3 = Q2u[(rw + g + 8)*QK_PITCH + kb + ti + 4];
            #pragma unroll
            for (int jn = 0; jn < 4; jn++) {
                const int nrow = cw*32 + jn*8 + g;
                uint32_t b0 = K2u[nrow*QK_PITCH + kb + ti    ];
                uint32_t b1 = K2u[nrow*QK_PITCH + kb + ti + 4];
                mma_tf32(sc[jn], a0, a1, a2, a3, b0, b1);
            }
        }

        // ---- epilogue: decay + causal mask, tf32 round, store S ----
        {
            const int dj = (i - j) * 64;
            uint32_t* S2u = (uint32_t*)S2;
            #pragma unroll
            for (int jn = 0; jn < 4; jn++) {
                const int col = cw*32 + jn*8 + 2*ti;
                const int rm0 = rw + g, rm1 = rw + g + 8;
                int e00 = dj + rm0 - col;
                int e01 = e00 - 1;
                int e10 = dj + rm1 - col;
                int e11 = e10 - 1;
                float d00 = (e00 >= 0) ? dec[e00] : 0.f;
                float d01 = (e01 >= 0) ? dec[e01] : 0.f;
                float d10 = (e10 >= 0) ? dec[e10] : 0.f;
                float d11 = (e11 >= 0) ? dec[e11] : 0.f;
                S2u[rm0*S_PITCH + col    ] = f2tf32(sc[jn][0] * d00);
                S2u[rm0*S_PITCH + col + 1] = f2tf32(sc[jn][1] * d01);
                S2u[rm1*S_PITCH + col    ] = f2tf32(sc[jn][2] * d10);
                S2u[rm1*S_PITCH + col + 1] = f2tf32(sc[jn][3] * d11);
            }
        }
        __syncthreads();

        // ---- O += S @ V: warp tile 16x64, K=64 ----
        const uint32_t* S2u = (const uint32_t*)S2;
        const uint32_t* Vsu = (const uint32_t*)Vs;
        #pragma unroll
        for (int kk = 0; kk < 8; kk++) {
            const int kb = kk * 8;
            uint32_t a0 = S2u[(rw + g    )*S_PITCH + kb + ti    ];
            uint32_t a1 = S2u[(rw + g + 8)*S_PITCH + kb + ti    ];
            uint32_t a2 = S2u[(rw + g    )*S_PITCH + kb + ti + 4];
            uint32_t a3 = S2u[(rw + g + 8)*S_PITCH + kb + ti + 4];
            #pragma unroll
            for (int jn = 0; jn < 8; jn++) {
                const int nc = cw*64 + jn*8 + g;
                uint32_t b0 = Vsu[(kb + ti    )*V_PITCH + nc];
                uint32_t b1 = Vsu[(kb + ti + 4)*V_PITCH + nc];
                mma_tf32(oc[jn], a0, a1, a2, a3, b0, b1);
            }
        }
    }

    // write O
    {
        const size_t row0 = qrow0 + rw + g;
        const size_t row1 = row0 + 8;
        #pragma unroll
        for (int jn = 0; jn < 8; jn++) {
            const int col = cw*64 + jn*8 + 2*ti;
            *(float2*)(out + row0*F + col) = make_float2(oc[jn][0], oc[jn][1]);
            *(float2*)(out + row1*F + col) = make_float2(oc[jn][2], oc[jn][3]);
        }
    }
}

// ---------------- launch ----------------
extern "C" void kernel_launch(void* const* d_in, const int* in_sizes, int n_in,
                              void* d_out, int out_size) {
    const float* x  = (const float*)d_in[0];
    const float* Wq = (const float*)d_in[1];
    const float* bq = (const float*)d_in[2];
    const float* Wk = (const float*)d_in[3];
    const float* bk = (const float*)d_in[4];
    const float* Wv = (const float*)d_in[5];
    const float* bv = (const float*)d_in[6];
    const float* th = (const float*)d_in[7];
    float* out = (float*)d_out;

    const size_t PROJ_SMEM = (size_t)PROJ_SMEM_FLOATS * sizeof(float);   // 101,376 B
    const size_t ATT_SMEM  = (size_t)ATT_SMEM_FLOATS * sizeof(float);    // 187,904 B

    cudaFuncSetAttribute(proj_mma_kernel, cudaFuncAttributeMaxDynamicSharedMemorySize, (int)PROJ_SMEM);
    cudaFuncSetAttribute(attn_mma_kernel, cudaFuncAttributeMaxDynamicSharedMemorySize, (int)ATT_SMEM);

    init_tables<<<S, F>>>(th);
    proj_mma_kernel<<<NQTILES, TPB, PROJ_SMEM>>>(x, Wq, bq, Wk, bk, Wv, bv);
    attn_mma_kernel<<<NQTILES, TPB, ATT_SMEM>>>(out);
}